// round 1
// baseline (speedup 1.0000x reference)
#include <cuda_runtime.h>

// Temporal cosine regularizer:
//   f_i = x_i / max(||x_i||, eps)
//   out = -0.02 / (N-1) * sum_{i=0}^{N-2} <f_i, f_{i+1}>
//       = -0.02 / (N-1) * sum_i <x_i, x_{i+1}> / (max(||x_i||,eps) * max(||x_{i+1}||,eps))
//
// HBM-bound: 512 MB read-once. Block owns RPB consecutive dot indices,
// streams RPB+1 rows once each (1.6% overlap overhead), previous row held
// in registers. Warp-shuffle partial reductions per row (no per-row
// __syncthreads), single block-level combine at the end. Deterministic
// two-stage reduction (no float atomics).

#define COLS     2048
#define RPB      64
#define NTHREADS 256

__device__ float g_partials[8192];

__device__ __forceinline__ float warp_reduce_f(float v) {
#pragma unroll
    for (int o = 16; o > 0; o >>= 1) v += __shfl_xor_sync(0xffffffffu, v, o);
    return v;
}

__global__ void __launch_bounds__(NTHREADS)
pair_dot_kernel(const float* __restrict__ x, int N) {
    __shared__ float s_sq[RPB + 1][8];
    __shared__ float s_dp[RPB + 1][8];

    const int tid  = threadIdx.x;
    const int lane = tid & 31;
    const int warp = tid >> 5;
    const int r0   = blockIdx.x * RPB;

    // Row r0: norm^2 only; becomes "prev".
    float prev[8];
    {
        const float4* rp = reinterpret_cast<const float4*>(x + (size_t)r0 * COLS);
        float4 a = __ldg(rp + tid);
        float4 b = __ldg(rp + tid + NTHREADS);
        prev[0] = a.x; prev[1] = a.y; prev[2] = a.z; prev[3] = a.w;
        prev[4] = b.x; prev[5] = b.y; prev[6] = b.z; prev[7] = b.w;
        float sq = 0.0f;
#pragma unroll
        for (int j = 0; j < 8; ++j) sq = fmaf(prev[j], prev[j], sq);
        sq = warp_reduce_f(sq);
        if (lane == 0) s_sq[0][warp] = sq;
    }

    // Rows r0+1 .. r0+RPB: norm^2 and dot with previous row.
#pragma unroll 4
    for (int rr = 1; rr <= RPB; ++rr) {
        const int r = r0 + rr;
        float sq = 0.0f, dp = 0.0f;
        if (r < N) {
            const float4* rp = reinterpret_cast<const float4*>(x + (size_t)r * COLS);
            float4 a = __ldg(rp + tid);
            float4 b = __ldg(rp + tid + NTHREADS);
            float cur[8] = {a.x, a.y, a.z, a.w, b.x, b.y, b.z, b.w};
#pragma unroll
            for (int j = 0; j < 8; ++j) {
                sq = fmaf(cur[j], cur[j], sq);
                dp = fmaf(cur[j], prev[j], dp);
                prev[j] = cur[j];
            }
        }
        sq = warp_reduce_f(sq);
        dp = warp_reduce_f(dp);
        if (lane == 0) { s_sq[rr][warp] = sq; s_dp[rr][warp] = dp; }
    }
    __syncthreads();

    // Warp 0: combine 8 warp-partials per row, form cosine terms, fp64 accumulate.
    if (warp == 0) {
        double acc = 0.0;
        for (int rr = 1 + lane; rr <= RPB; rr += 32) {
            if (r0 + rr < N) {  // dot index r0+rr-1 must be <= N-2
                float n2a = 0.0f, n2b = 0.0f, d8 = 0.0f;
#pragma unroll
                for (int w = 0; w < 8; ++w) {
                    n2a += s_sq[rr - 1][w];
                    n2b += s_sq[rr][w];
                    d8  += s_dp[rr][w];
                }
                float na = fmaxf(sqrtf(n2a), 1e-12f);
                float nb = fmaxf(sqrtf(n2b), 1e-12f);
                acc += (double)(d8 / (na * nb));
            }
        }
#pragma unroll
        for (int o = 16; o > 0; o >>= 1)
            acc += __shfl_xor_sync(0xffffffffu, acc, o);
        if (lane == 0) g_partials[blockIdx.x] = (float)acc;
    }
}

__global__ void __launch_bounds__(256)
finalize_kernel(int nblocks, int N, float* __restrict__ out) {
    __shared__ double s[256];
    double a = 0.0;
    for (int i = threadIdx.x; i < nblocks; i += 256) a += (double)g_partials[i];
    s[threadIdx.x] = a;
    __syncthreads();
    for (int o = 128; o > 0; o >>= 1) {
        if (threadIdx.x < o) s[threadIdx.x] += s[threadIdx.x + o];
        __syncthreads();
    }
    if (threadIdx.x == 0)
        out[0] = (float)(-2.0 * 0.01 * s[0] / (double)(N - 1));
}

extern "C" void kernel_launch(void* const* d_in, const int* in_sizes, int n_in,
                              void* d_out, int out_size) {
    const float* x = (const float*)d_in[0];
    const int N = in_sizes[0] / COLS;           // 65536
    const int nblocks = (N - 1 + RPB - 1) / RPB; // 1024
    pair_dot_kernel<<<nblocks, NTHREADS>>>(x, N);
    finalize_kernel<<<1, 256>>>(nblocks, N, (float*)d_out);
}

// round 2
// speedup vs baseline: 1.0246x; 1.0246x over previous
#include <cuda_runtime.h>

// Temporal cosine regularizer, single fused kernel.
//   out = -0.02/(N-1) * sum_i <x_i,x_{i+1}> / (max(||x_i||,eps)*max(||x_{i+1}||,eps))
//
// HBM-bound: 512 MB read-once. Each block owns RPB consecutive dot indices,
// streams RPB+1 rows (1.6% boundary overlap), previous row in registers,
// warp-shuffle partial reductions (no per-row __syncthreads). Last finishing
// block performs the deterministic final reduction over per-block partials
// (fixed-order tree, independent of which block runs it) — removes the
// ~6us second-launch tail seen in R1.

#define COLS     2048
#define RPB      64
#define NTHREADS 256

__device__ float        g_partials[8192];
__device__ unsigned int g_count = 0;

__device__ __forceinline__ float warp_reduce_f(float v) {
#pragma unroll
    for (int o = 16; o > 0; o >>= 1) v += __shfl_xor_sync(0xffffffffu, v, o);
    return v;
}

__global__ void __launch_bounds__(NTHREADS)
pair_dot_fused_kernel(const float* __restrict__ x, int N, float* __restrict__ out) {
    __shared__ float s_sq[RPB + 1][8];
    __shared__ float s_dp[RPB + 1][8];
    __shared__ bool  s_last;

    const int tid  = threadIdx.x;
    const int lane = tid & 31;
    const int warp = tid >> 5;
    const int r0   = blockIdx.x * RPB;

    // Row r0: norm^2 only; becomes "prev".
    float prev[8];
    {
        const float4* rp = reinterpret_cast<const float4*>(x + (size_t)r0 * COLS);
        float4 a = __ldg(rp + tid);
        float4 b = __ldg(rp + tid + NTHREADS);
        prev[0] = a.x; prev[1] = a.y; prev[2] = a.z; prev[3] = a.w;
        prev[4] = b.x; prev[5] = b.y; prev[6] = b.z; prev[7] = b.w;
        float sq = 0.0f;
#pragma unroll
        for (int j = 0; j < 8; ++j) sq = fmaf(prev[j], prev[j], sq);
        sq = warp_reduce_f(sq);
        if (lane == 0) s_sq[0][warp] = sq;
    }

    // Rows r0+1 .. r0+RPB: norm^2 and dot with previous row.
#pragma unroll 4
    for (int rr = 1; rr <= RPB; ++rr) {
        const int r = r0 + rr;
        float sq = 0.0f, dp = 0.0f;
        if (r < N) {
            const float4* rp = reinterpret_cast<const float4*>(x + (size_t)r * COLS);
            float4 a = __ldg(rp + tid);
            float4 b = __ldg(rp + tid + NTHREADS);
            float cur[8] = {a.x, a.y, a.z, a.w, b.x, b.y, b.z, b.w};
#pragma unroll
            for (int j = 0; j < 8; ++j) {
                sq = fmaf(cur[j], cur[j], sq);
                dp = fmaf(cur[j], prev[j], dp);
                prev[j] = cur[j];
            }
        }
        sq = warp_reduce_f(sq);
        dp = warp_reduce_f(dp);
        if (lane == 0) { s_sq[rr][warp] = sq; s_dp[rr][warp] = dp; }
    }
    __syncthreads();

    // Warp 0: combine 8 warp-partials per row, cosine terms, fp64 accumulate.
    if (warp == 0) {
        double acc = 0.0;
        for (int rr = 1 + lane; rr <= RPB; rr += 32) {
            if (r0 + rr < N) {  // dot index r0+rr-1 must be <= N-2
                float n2a = 0.0f, n2b = 0.0f, d8 = 0.0f;
#pragma unroll
                for (int w = 0; w < 8; ++w) {
                    n2a += s_sq[rr - 1][w];
                    n2b += s_sq[rr][w];
                    d8  += s_dp[rr][w];
                }
                float na = fmaxf(sqrtf(n2a), 1e-12f);
                float nb = fmaxf(sqrtf(n2b), 1e-12f);
                acc += (double)(d8 / (na * nb));
            }
        }
#pragma unroll
        for (int o = 16; o > 0; o >>= 1)
            acc += __shfl_xor_sync(0xffffffffu, acc, o);
        if (lane == 0) g_partials[blockIdx.x] = (float)acc;
    }

    // ---- last-block-done: fold the final reduction into this kernel ----
    __threadfence();  // make g_partials[blockIdx.x] visible before counting
    if (tid == 0) {
        unsigned int prev_cnt = atomicAdd(&g_count, 1u);
        s_last = (prev_cnt == gridDim.x - 1);
    }
    __syncthreads();

    if (s_last) {
        __shared__ double s[NTHREADS];
        const int nb = gridDim.x;
        double a = 0.0;
        for (int i = tid; i < nb; i += NTHREADS)
            a += (double)__ldcg(&g_partials[i]);   // L2 read: fresh across SMs
        s[tid] = a;
        __syncthreads();
#pragma unroll
        for (int o = NTHREADS / 2; o > 0; o >>= 1) {
            if (tid < o) s[tid] += s[tid + o];
            __syncthreads();
        }
        if (tid == 0) {
            out[0] = (float)(-2.0 * 0.01 * s[0] / (double)(N - 1));
            g_count = 0;  // reset for next graph replay
        }
    }
}

extern "C" void kernel_launch(void* const* d_in, const int* in_sizes, int n_in,
                              void* d_out, int out_size) {
    const float* x = (const float*)d_in[0];
    const int N = in_sizes[0] / COLS;            // 65536
    const int nblocks = (N - 1 + RPB - 1) / RPB; // 1024
    pair_dot_fused_kernel<<<nblocks, NTHREADS>>>(x, N, (float*)d_out);
}